// round 14
// baseline (speedup 1.0000x reference)
#include <cuda_runtime.h>

#define CHUNKS 16
#define RES_DIM 8192
#define NSE 1342177
#define BLOCKS_X 18               // 18*16 = 288 blocks (2/SM, one wave)
#define TPB 1024
#define SMEM_BYTES (2 * RES_DIM * sizeof(float))   // sacc + sstate = 64 KB
#define TICKET_F4 (TPB * 2)       // float4 elements per ticket (8192 nnz)

// Global accumulator, L2-resident (512 KB). Invariant: zero at kernel_launch
// entry (loader zero-init; the finalizing block re-zeros it every launch).
__device__ float g_gacc[CHUNKS * RES_DIM];
// Per-chunk arrival + ticket counters; same zero-at-entry invariant.
__device__ unsigned int g_count[CHUNKS];
__device__ unsigned int g_ticket[CHUNKS];

// Fused kernel: COO scatter (smem privatization + smem-staged state) with
// DYNAMIC ticket-based work distribution (compresses block-completion spread),
// vector-RED flush into g_gacc, and in-kernel finalize by the last-arriving
// block of each chunk.
__global__ void __launch_bounds__(TPB, 2)
ptd_scatter_kernel(const float* __restrict__ vals,
                   const int*   __restrict__ rows,
                   const int*   __restrict__ cols,
                   const float* __restrict__ state,
                   const float* __restrict__ proj,
                   float*       __restrict__ out) {
    extern __shared__ float smem[];
    float* sacc   = smem;             // [RES_DIM]
    float* sstate = smem + RES_DIM;   // [RES_DIM]
    __shared__ unsigned int s_last;
    __shared__ unsigned int s_ticket;

    const int chunk = blockIdx.y;
    const size_t base = (size_t)chunk * NSE;

    // Zero accumulator + stage state (both vectorized).
    {
        float4* a4 = reinterpret_cast<float4*>(sacc);
        float4* s4 = reinterpret_cast<float4*>(sstate);
        const float4* st4 = reinterpret_cast<const float4*>(state + (size_t)chunk * RES_DIM);
        #pragma unroll
        for (int i = threadIdx.x; i < RES_DIM / 4; i += TPB) {
            a4[i] = make_float4(0.f, 0.f, 0.f, 0.f);
            s4[i] = st4[i];
        }
    }
    __syncthreads();

    // Alignment split (base not 16B-aligned since NSE is odd).
    const int head = (int)((4 - (base & 3)) & 3);
    const int nvec = (NSE - head) >> 2;
    const int tail = NSE - head - (nvec << 2);

    const float4* __restrict__ v4 = reinterpret_cast<const float4*>(vals + base + head);
    const int4*   __restrict__ r4 = reinterpret_cast<const int4*>(rows + base + head);
    const int4*   __restrict__ c4 = reinterpret_cast<const int4*>(cols + base + head);

    // Head + tail scalars (block x==0 only).
    if (blockIdx.x == 0) {
        if (threadIdx.x < head) {
            const size_t k = base + threadIdx.x;
            atomicAdd(sacc + rows[k], vals[k] * sstate[cols[k]]);
        }
        if (threadIdx.x >= 32 && threadIdx.x < 32 + tail) {
            const size_t k = base + head + ((size_t)nvec << 2) + (threadIdx.x - 32);
            atomicAdd(sacc + rows[k], vals[k] * sstate[cols[k]]);
        }
    }

    // Dynamic ticket loop: each ticket = TICKET_F4 contiguous float4 (8192 nnz).
    const int num_tickets = (nvec + TICKET_F4 - 1) / TICKET_F4;
    for (;;) {
        __syncthreads();                 // protect s_ticket (WAR hazard)
        if (threadIdx.x == 0)
            s_ticket = atomicAdd(&g_ticket[chunk], 1u);
        __syncthreads();
        const unsigned int t = s_ticket;
        if (t >= (unsigned int)num_tickets) break;

        const int i0 = (int)t * TICKET_F4 + threadIdx.x;
        const int i1 = i0 + TPB;

        if ((int)(t + 1) * TICKET_F4 <= nvec) {
            // Full ticket: 8 nnz/thread, 6 streaming LDG.128 up front.
            float4 va = __ldcs(v4 + i0); float4 vb = __ldcs(v4 + i1);
            int4   ca = __ldcs(c4 + i0); int4   cb = __ldcs(c4 + i1);
            int4   ra = __ldcs(r4 + i0); int4   rb = __ldcs(r4 + i1);

            float fa0 = va.x * sstate[ca.x], fa1 = va.y * sstate[ca.y];
            float fa2 = va.z * sstate[ca.z], fa3 = va.w * sstate[ca.w];
            float fb0 = vb.x * sstate[cb.x], fb1 = vb.y * sstate[cb.y];
            float fb2 = vb.z * sstate[cb.z], fb3 = vb.w * sstate[cb.w];

            atomicAdd(sacc + ra.x, fa0);
            atomicAdd(sacc + ra.y, fa1);
            atomicAdd(sacc + ra.z, fa2);
            atomicAdd(sacc + ra.w, fa3);
            atomicAdd(sacc + rb.x, fb0);
            atomicAdd(sacc + rb.y, fb1);
            atomicAdd(sacc + rb.z, fb2);
            atomicAdd(sacc + rb.w, fb3);
        } else {
            // Partial last ticket: bounds-checked.
            if (i0 < nvec) {
                float4 va = __ldcs(v4 + i0);
                int4   ca = __ldcs(c4 + i0);
                int4   ra = __ldcs(r4 + i0);
                atomicAdd(sacc + ra.x, va.x * sstate[ca.x]);
                atomicAdd(sacc + ra.y, va.y * sstate[ca.y]);
                atomicAdd(sacc + ra.z, va.z * sstate[ca.z]);
                atomicAdd(sacc + ra.w, va.w * sstate[ca.w]);
            }
            if (i1 < nvec) {
                float4 vb = __ldcs(v4 + i1);
                int4   cb = __ldcs(c4 + i1);
                int4   rb = __ldcs(r4 + i1);
                atomicAdd(sacc + rb.x, vb.x * sstate[cb.x]);
                atomicAdd(sacc + rb.y, vb.y * sstate[cb.y]);
                atomicAdd(sacc + rb.z, vb.z * sstate[cb.z]);
                atomicAdd(sacc + rb.w, vb.w * sstate[cb.w]);
            }
        }
    }
    __syncthreads();

    // Flush: vector REDs (RED.E.ADD.F32x4) into the L2-resident accumulator.
    {
        float4* dst = reinterpret_cast<float4*>(g_gacc + (size_t)chunk * RES_DIM);
        const float4* src = reinterpret_cast<const float4*>(sacc);
        #pragma unroll
        for (int k = threadIdx.x; k < RES_DIM / 4; k += TPB) {
            atomicAdd(dst + k, src[k]);
        }
    }

    // Arrival protocol: order the REDs, then bump this chunk's counter.
    __threadfence();
    __syncthreads();
    if (threadIdx.x == 0) {
        unsigned int old = atomicAdd(&g_count[chunk], 1u);
        s_last = (old == BLOCKS_X - 1) ? 1u : 0u;
        if (s_last) {
            g_count[chunk] = 0;           // restore invariants
            g_ticket[chunk] = 0;
        }
    }
    __syncthreads();

    // Last-arriving block of this chunk: finalize (64 KB of reads total).
    // out = taylor_tanh(proj + g_gacc); then re-zero g_gacc.
    if (s_last) {
        const float t  = tanhf(1.6f);
        const float t2 = t * t;
        const float t3 = t2 * t;
        const float t4 = t2 * t2;
        const float t6 = t4 * t2;
        const float c0 = t;
        const float c1 = 1.0f - t2;
        const float c2 = t3 - t;
        const float c3 = -t4 + (4.0f / 3.0f) * t2 - (1.0f / 3.0f);
        const float c4 = (t / 3.0f) * (3.0f * t4 - 5.0f * t2 + 2.0f);
        const float c5 = -t6 + 2.0f * t4 - (17.0f / 15.0f) * t2 + (2.0f / 15.0f);

        float4* __restrict__ ga4 = reinterpret_cast<float4*>(
            g_gacc + (size_t)chunk * RES_DIM);
        const float4* __restrict__ pr4 = reinterpret_cast<const float4*>(
            proj + (size_t)chunk * RES_DIM);
        float4* __restrict__ o4 = reinterpret_cast<float4*>(
            out + (size_t)chunk * RES_DIM);

        #pragma unroll
        for (int k = threadIdx.x; k < RES_DIM / 4; k += TPB) {
            float4 z = pr4[k];
            float4 g = __ldcg(ga4 + k);   // read at L2 (coherence point for REDs)
            z.x += g.x; z.y += g.y; z.z += g.z; z.w += g.w;
            float4 r;
            r.x = fmaf(z.x, fmaf(z.x, fmaf(z.x, fmaf(z.x, fmaf(z.x, c5, c4), c3), c2), c1), c0);
            r.y = fmaf(z.y, fmaf(z.y, fmaf(z.y, fmaf(z.y, fmaf(z.y, c5, c4), c3), c2), c1), c0);
            r.z = fmaf(z.z, fmaf(z.z, fmaf(z.z, fmaf(z.z, fmaf(z.z, c5, c4), c3), c2), c1), c0);
            r.w = fmaf(z.w, fmaf(z.w, fmaf(z.w, fmaf(z.w, fmaf(z.w, c5, c4), c3), c2), c1), c0);
            o4[k] = r;
            ga4[k] = make_float4(0.f, 0.f, 0.f, 0.f);   // restore invariant
        }
    }
}

extern "C" void kernel_launch(void* const* d_in, const int* in_sizes, int n_in,
                              void* d_out, int out_size) {
    const float* proj  = (const float*)d_in[0];
    const float* state = (const float*)d_in[1];
    const float* vals  = (const float*)d_in[2];
    const int*   rows  = (const int*)d_in[3];
    const int*   cols  = (const int*)d_in[4];
    float* out = (float*)d_out;

    // 64 KB dynamic smem per block (static limit is 48 KB). Idempotent.
    cudaFuncSetAttribute(ptd_scatter_kernel,
                         cudaFuncAttributeMaxDynamicSharedMemorySize, SMEM_BYTES);

    dim3 grid(BLOCKS_X, CHUNKS);   // 288 blocks x 1024 threads, 2/SM
    ptd_scatter_kernel<<<grid, TPB, SMEM_BYTES>>>(vals, rows, cols, state, proj, out);
}

// round 16
// speedup vs baseline: 1.3216x; 1.3216x over previous
#include <cuda_runtime.h>

#define CHUNKS 16
#define RES_DIM 8192
#define NSE 1342177
#define BLOCKS_X 18               // 18*16 = 288 blocks (2/SM, one wave)
#define TPB 1024
#define SMEM_BYTES (2 * RES_DIM * sizeof(float))   // sacc + sstate = 64 KB
#define WT_F4 512                 // float4 per warp-ticket (2048 nnz)

// Global accumulator, L2-resident (512 KB). Invariant: zero at kernel_launch
// entry (loader zero-init; the finalizing block re-zeros it every launch).
__device__ float g_gacc[CHUNKS * RES_DIM];
// Per-chunk arrival counters; same zero-at-entry invariant.
__device__ unsigned int g_count[CHUNKS];
// Per-chunk ticket counters, one per 128B line; same zero-at-entry invariant.
__device__ unsigned int g_ticket[CHUNKS * 32];

// Fused kernel: COO scatter (smem privatization + smem-staged state) with
// warp-level dynamic tickets (no barriers in the work loop), vector-RED flush
// into g_gacc, in-kernel finalize by the last-arriving block of each chunk.
__global__ void __launch_bounds__(TPB, 2)
ptd_scatter_kernel(const float* __restrict__ vals,
                   const int*   __restrict__ rows,
                   const int*   __restrict__ cols,
                   const float* __restrict__ state,
                   const float* __restrict__ proj,
                   float*       __restrict__ out) {
    extern __shared__ float smem[];
    float* sacc   = smem;             // [RES_DIM]
    float* sstate = smem + RES_DIM;   // [RES_DIM]
    __shared__ unsigned int s_last;

    const int chunk = blockIdx.y;
    const size_t base = (size_t)chunk * NSE;
    const int lane = threadIdx.x & 31;

    // Zero accumulator + stage state (both vectorized).
    {
        float4* a4 = reinterpret_cast<float4*>(sacc);
        float4* s4 = reinterpret_cast<float4*>(sstate);
        const float4* st4 = reinterpret_cast<const float4*>(state + (size_t)chunk * RES_DIM);
        #pragma unroll
        for (int i = threadIdx.x; i < RES_DIM / 4; i += TPB) {
            a4[i] = make_float4(0.f, 0.f, 0.f, 0.f);
            s4[i] = st4[i];
        }
    }
    __syncthreads();

    // Alignment split (base not 16B-aligned since NSE is odd).
    const int head = (int)((4 - (base & 3)) & 3);
    const int nvec = (NSE - head) >> 2;
    const int tail = NSE - head - (nvec << 2);

    const float4* __restrict__ v4 = reinterpret_cast<const float4*>(vals + base + head);
    const int4*   __restrict__ r4 = reinterpret_cast<const int4*>(rows + base + head);
    const int4*   __restrict__ c4 = reinterpret_cast<const int4*>(cols + base + head);

    // Head + tail scalars (block x==0 only).
    if (blockIdx.x == 0) {
        if (threadIdx.x < head) {
            const size_t k = base + threadIdx.x;
            atomicAdd(sacc + rows[k], vals[k] * sstate[cols[k]]);
        }
        if (threadIdx.x >= 32 && threadIdx.x < 32 + tail) {
            const size_t k = base + head + ((size_t)nvec << 2) + (threadIdx.x - 32);
            atomicAdd(sacc + rows[k], vals[k] * sstate[cols[k]]);
        }
    }

    // Warp-level dynamic ticket loop: no block barriers inside.
    // Each ticket = WT_F4 contiguous float4; 8 pair-iterations per warp.
    const int num_full    = nvec / WT_F4;
    const int num_tickets = (nvec + WT_F4 - 1) / WT_F4;
    unsigned int* tick = &g_ticket[chunk * 32];

    for (;;) {
        unsigned int t = 0;                       // initialized: no UB at shfl
        if (lane == 0) t = atomicAdd(tick, 1u);
        t = __shfl_sync(0xffffffffu, t, 0);
        if (t >= (unsigned int)num_tickets) break;

        const int bf4 = (int)t * WT_F4;

        if ((int)t < num_full) {
            #pragma unroll
            for (int k = 0; k < WT_F4 / 32; k += 2) {
                const int ia = bf4 + k * 32 + lane;
                const int ib = ia + 32;
                float4 va = __ldcs(v4 + ia); float4 vb = __ldcs(v4 + ib);
                int4   ca = __ldcs(c4 + ia); int4   cb = __ldcs(c4 + ib);
                int4   ra = __ldcs(r4 + ia); int4   rb = __ldcs(r4 + ib);

                float fa0 = va.x * sstate[ca.x], fa1 = va.y * sstate[ca.y];
                float fa2 = va.z * sstate[ca.z], fa3 = va.w * sstate[ca.w];
                float fb0 = vb.x * sstate[cb.x], fb1 = vb.y * sstate[cb.y];
                float fb2 = vb.z * sstate[cb.z], fb3 = vb.w * sstate[cb.w];

                atomicAdd(sacc + ra.x, fa0);
                atomicAdd(sacc + ra.y, fa1);
                atomicAdd(sacc + ra.z, fa2);
                atomicAdd(sacc + ra.w, fa3);
                atomicAdd(sacc + rb.x, fb0);
                atomicAdd(sacc + rb.y, fb1);
                atomicAdd(sacc + rb.z, fb2);
                atomicAdd(sacc + rb.w, fb3);
            }
        } else {
            // Partial last ticket: bounds-checked.
            for (int k = 0; k < WT_F4 / 32; k++) {
                const int ia = bf4 + k * 32 + lane;
                if (ia < nvec) {
                    float4 va = __ldcs(v4 + ia);
                    int4   ca = __ldcs(c4 + ia);
                    int4   ra = __ldcs(r4 + ia);
                    atomicAdd(sacc + ra.x, va.x * sstate[ca.x]);
                    atomicAdd(sacc + ra.y, va.y * sstate[ca.y]);
                    atomicAdd(sacc + ra.z, va.z * sstate[ca.z]);
                    atomicAdd(sacc + ra.w, va.w * sstate[ca.w]);
                }
            }
        }
    }
    __syncthreads();

    // Flush: vector REDs (RED.E.ADD.F32x4) into the L2-resident accumulator.
    {
        float4* dst = reinterpret_cast<float4*>(g_gacc + (size_t)chunk * RES_DIM);
        const float4* src = reinterpret_cast<const float4*>(sacc);
        #pragma unroll
        for (int k = threadIdx.x; k < RES_DIM / 4; k += TPB) {
            atomicAdd(dst + k, src[k]);
        }
    }

    // Arrival protocol: release-fence the REDs, then bump this chunk's counter.
    __threadfence();
    __syncthreads();
    if (threadIdx.x == 0) {
        unsigned int old = atomicAdd(&g_count[chunk], 1u);
        s_last = (old == BLOCKS_X - 1) ? 1u : 0u;
        if (s_last) {
            g_count[chunk] = 0;           // restore invariants
            *tick = 0;
        }
    }
    __syncthreads();

    // Last-arriving block of this chunk: finalize (64 KB of reads total).
    if (s_last) {
        __threadfence();   // acquire: order other blocks' REDs before our reads

        const float t  = tanhf(1.6f);
        const float t2 = t * t;
        const float t3 = t2 * t;
        const float t4 = t2 * t2;
        const float t6 = t4 * t2;
        const float c0 = t;
        const float c1 = 1.0f - t2;
        const float c2 = t3 - t;
        const float c3 = -t4 + (4.0f / 3.0f) * t2 - (1.0f / 3.0f);
        const float c4 = (t / 3.0f) * (3.0f * t4 - 5.0f * t2 + 2.0f);
        const float c5 = -t6 + 2.0f * t4 - (17.0f / 15.0f) * t2 + (2.0f / 15.0f);

        float4* __restrict__ ga4 = reinterpret_cast<float4*>(
            g_gacc + (size_t)chunk * RES_DIM);
        const float4* __restrict__ pr4 = reinterpret_cast<const float4*>(
            proj + (size_t)chunk * RES_DIM);
        float4* __restrict__ o4 = reinterpret_cast<float4*>(
            out + (size_t)chunk * RES_DIM);

        #pragma unroll
        for (int k = threadIdx.x; k < RES_DIM / 4; k += TPB) {
            float4 z = pr4[k];
            float4 g = __ldcg(ga4 + k);   // read at L2 (coherence point for REDs)
            z.x += g.x; z.y += g.y; z.z += g.z; z.w += g.w;
            float4 r;
            r.x = fmaf(z.x, fmaf(z.x, fmaf(z.x, fmaf(z.x, fmaf(z.x, c5, c4), c3), c2), c1), c0);
            r.y = fmaf(z.y, fmaf(z.y, fmaf(z.y, fmaf(z.y, fmaf(z.y, c5, c4), c3), c2), c1), c0);
            r.z = fmaf(z.z, fmaf(z.z, fmaf(z.z, fmaf(z.z, fmaf(z.z, c5, c4), c3), c2), c1), c0);
            r.w = fmaf(z.w, fmaf(z.w, fmaf(z.w, fmaf(z.w, fmaf(z.w, c5, c4), c3), c2), c1), c0);
            o4[k] = r;
            ga4[k] = make_float4(0.f, 0.f, 0.f, 0.f);   // restore invariant
        }
    }
}

extern "C" void kernel_launch(void* const* d_in, const int* in_sizes, int n_in,
                              void* d_out, int out_size) {
    const float* proj  = (const float*)d_in[0];
    const float* state = (const float*)d_in[1];
    const float* vals  = (const float*)d_in[2];
    const int*   rows  = (const int*)d_in[3];
    const int*   cols  = (const int*)d_in[4];
    float* out = (float*)d_out;

    // 64 KB dynamic smem per block (static limit is 48 KB). Idempotent.
    cudaFuncSetAttribute(ptd_scatter_kernel,
                         cudaFuncAttributeMaxDynamicSharedMemorySize, SMEM_BYTES);

    dim3 grid(BLOCKS_X, CHUNKS);   // 288 blocks x 1024 threads, 2/SM
    ptd_scatter_kernel<<<grid, TPB, SMEM_BYTES>>>(vals, rows, cols, state, proj, out);
}

// round 17
// speedup vs baseline: 1.5662x; 1.1851x over previous
#include <cuda_runtime.h>

#define CHUNKS 16
#define RES_DIM 8192
#define NSE 1342177
#define BLOCKS_X 18               // partials per chunk; 18*16 = 288 blocks (2/SM)
#define TPB 1024
#define SMEM_BYTES (2 * RES_DIM * sizeof(float))   // sacc + sstate = 64 KB

// Per-block partial accumulators: 16 chunks x 18 blocks x 8192 floats = 9.4 MB.
__device__ float g_part[CHUNKS * BLOCKS_X * RES_DIM];

// Kernel 1: COO scatter with shared-memory privatization AND smem-staged state.
// Static equal partition (fastest measured variant), near the per-SM
// instruction-issue/ATOMS floor; 32 regs/thread = full regfile at 2048 thr/SM.
__global__ void __launch_bounds__(TPB, 2)
ptd_scatter_kernel(const float* __restrict__ vals,
                   const int*   __restrict__ rows,
                   const int*   __restrict__ cols,
                   const float* __restrict__ state) {
    extern __shared__ float smem[];
    float* sacc   = smem;             // [RES_DIM]
    float* sstate = smem + RES_DIM;   // [RES_DIM]

    const int chunk = blockIdx.y;
    const size_t base = (size_t)chunk * NSE;

    // Zero accumulator + stage state (both vectorized).
    {
        float4* a4 = reinterpret_cast<float4*>(sacc);
        float4* s4 = reinterpret_cast<float4*>(sstate);
        const float4* st4 = reinterpret_cast<const float4*>(state + (size_t)chunk * RES_DIM);
        #pragma unroll
        for (int i = threadIdx.x; i < RES_DIM / 4; i += TPB) {
            a4[i] = make_float4(0.f, 0.f, 0.f, 0.f);
            s4[i] = st4[i];
        }
    }
    __syncthreads();

    // Alignment split (base not 16B-aligned since NSE is odd).
    const int head = (int)((4 - (base & 3)) & 3);
    const int nvec = (NSE - head) >> 2;
    const int tail = NSE - head - (nvec << 2);

    const float4* __restrict__ v4 = reinterpret_cast<const float4*>(vals + base + head);
    const int4*   __restrict__ r4 = reinterpret_cast<const int4*>(rows + base + head);
    const int4*   __restrict__ c4 = reinterpret_cast<const int4*>(cols + base + head);

    const int stride = BLOCKS_X * TPB;
    int i = blockIdx.x * TPB + threadIdx.x;

    // Main loop, unrolled x2 (8 nnz/thread/iter): 6 streaming LDG.128, then
    // 8 LDS gathers and 8 smem atomics.
    for (; i + stride < nvec; i += 2 * stride) {
        const int j = i + stride;
        float4 va = __ldcs(v4 + i); float4 vb = __ldcs(v4 + j);
        int4   ca = __ldcs(c4 + i); int4   cb = __ldcs(c4 + j);
        int4   ra = __ldcs(r4 + i); int4   rb = __ldcs(r4 + j);

        float fa0 = va.x * sstate[ca.x], fa1 = va.y * sstate[ca.y];
        float fa2 = va.z * sstate[ca.z], fa3 = va.w * sstate[ca.w];
        float fb0 = vb.x * sstate[cb.x], fb1 = vb.y * sstate[cb.y];
        float fb2 = vb.z * sstate[cb.z], fb3 = vb.w * sstate[cb.w];

        atomicAdd(sacc + ra.x, fa0);
        atomicAdd(sacc + ra.y, fa1);
        atomicAdd(sacc + ra.z, fa2);
        atomicAdd(sacc + ra.w, fa3);
        atomicAdd(sacc + rb.x, fb0);
        atomicAdd(sacc + rb.y, fb1);
        atomicAdd(sacc + rb.z, fb2);
        atomicAdd(sacc + rb.w, fb3);
    }
    for (; i < nvec; i += stride) {
        float4 va = __ldcs(v4 + i);
        int4   ca = __ldcs(c4 + i);
        int4   ra = __ldcs(r4 + i);
        atomicAdd(sacc + ra.x, va.x * sstate[ca.x]);
        atomicAdd(sacc + ra.y, va.y * sstate[ca.y]);
        atomicAdd(sacc + ra.z, va.z * sstate[ca.z]);
        atomicAdd(sacc + ra.w, va.w * sstate[ca.w]);
    }

    // Head + tail scalars (block x==0 only, into its own sacc).
    if (blockIdx.x == 0) {
        if (threadIdx.x < head) {
            const size_t k = base + threadIdx.x;
            atomicAdd(sacc + rows[k], vals[k] * sstate[cols[k]]);
        }
        if (threadIdx.x >= 32 && threadIdx.x < 32 + tail) {
            const size_t k = base + head + ((size_t)nvec << 2) + (threadIdx.x - 32);
            atomicAdd(sacc + rows[k], vals[k] * sstate[cols[k]]);
        }
    }
    __syncthreads();

    // Flush: plain vectorized stores to this block's scratch slice (2048 STG.128).
    {
        float4* dst = reinterpret_cast<float4*>(
            g_part + ((size_t)chunk * BLOCKS_X + blockIdx.x) * RES_DIM);
        const float4* src = reinterpret_cast<const float4*>(sacc);
        #pragma unroll
        for (int k = threadIdx.x; k < RES_DIM / 4; k += TPB)
            dst[k] = src[k];
    }
}

// Kernel 2: finalize.  out[i] = taylor_tanh(proj[i] + sum_b partials[b][i]).
// Scalarized: one thread per output float (131072 threads) to cover L2
// latency; all loads coalesced; two independent accumulation chains.
__global__ void ptd_finalize_kernel(const float* __restrict__ proj,
                                    float* __restrict__ out) {
    const int i = blockIdx.x * blockDim.x + threadIdx.x;   // float index
    if (i >= CHUNKS * RES_DIM) return;

    const int chunk = i >> 13;                 // i / RES_DIM
    const int ofs   = i & (RES_DIM - 1);       // i % RES_DIM

    const float* __restrict__ p = g_part + (size_t)chunk * BLOCKS_X * RES_DIM + ofs;
    float z0 = proj[i];
    float z1 = 0.f;
    #pragma unroll
    for (int b = 0; b < BLOCKS_X; b += 2) {
        z0 += __ldcs(p + (size_t)b * RES_DIM);
        z1 += __ldcs(p + (size_t)(b + 1) * RES_DIM);
    }
    float z = z0 + z1;

    const float t  = tanhf(1.6f);
    const float t2 = t * t;
    const float t3 = t2 * t;
    const float t4 = t2 * t2;
    const float t6 = t4 * t2;
    const float c0 = t;
    const float c1 = 1.0f - t2;
    const float c2 = t3 - t;
    const float c3 = -t4 + (4.0f / 3.0f) * t2 - (1.0f / 3.0f);
    const float c4 = (t / 3.0f) * (3.0f * t4 - 5.0f * t2 + 2.0f);
    const float c5 = -t6 + 2.0f * t4 - (17.0f / 15.0f) * t2 + (2.0f / 15.0f);

    out[i] = fmaf(z, fmaf(z, fmaf(z, fmaf(z, fmaf(z, c5, c4), c3), c2), c1), c0);
}

extern "C" void kernel_launch(void* const* d_in, const int* in_sizes, int n_in,
                              void* d_out, int out_size) {
    const float* proj  = (const float*)d_in[0];
    const float* state = (const float*)d_in[1];
    const float* vals  = (const float*)d_in[2];
    const int*   rows  = (const int*)d_in[3];
    const int*   cols  = (const int*)d_in[4];
    float* out = (float*)d_out;

    // 64 KB dynamic smem per block (static limit is 48 KB). Idempotent.
    cudaFuncSetAttribute(ptd_scatter_kernel,
                         cudaFuncAttributeMaxDynamicSharedMemorySize, SMEM_BYTES);

    {
        dim3 grid(BLOCKS_X, CHUNKS);   // 288 blocks x 1024 threads, 2/SM
        ptd_scatter_kernel<<<grid, TPB, SMEM_BYTES>>>(vals, rows, cols, state);
    }
    {
        int n = CHUNKS * RES_DIM;      // 131072 threads, one per output float
        ptd_finalize_kernel<<<(n + 255) / 256, 256>>>(proj, out);
    }
}